// round 11
// baseline (speedup 1.0000x reference)
#include <cuda_runtime.h>
#include <cuda_bf16.h>
#include <mma.h>
#include <stdint.h>
#include <math.h>

using namespace nvcuda;

#define N_ROWS 8192
#define F_IN   784
#define KPAD   800    // F_IN padded to multiple of 32
#define H      128
#define JH     4096   // j-half size for k5
#define JT     1024   // j-tile size for k4

typedef unsigned long long ull;

// ---------------- scratch (static device globals; no allocation) -------------
__device__ float         g_o1[N_ROWS * H];   // selu(fc1) activations (4 MB)
__device__ __nv_bfloat16 g_wh[H * KPAD];     // w hi split, zero-padded
__device__ __nv_bfloat16 g_wl[H * KPAD];     // w lo split
__device__ float2 g_o[N_ROWS];               // final 2-D embedding
__device__ double g_sum[H];
__device__ double g_sumsq[H];
__device__ double g_denom;                   // S = sum_{i<j} 1/(1+d_ij)

// ---------------- helpers ----------------------------------------------------
__device__ __forceinline__ float frcp(float x) {
    float r; asm("rcp.approx.f32 %0, %1;" : "=f"(r) : "f"(x)); return r;
}
__device__ __forceinline__ float selu_f(float v) {
    const float sc = 1.0507009873554805f, al = 1.6732632423543772f;
    return v > 0.f ? sc * v : sc * al * expm1f(v);
}

#define FMA_F32X2(d, a, b, c) \
    asm("fma.rn.f32x2 %0, %1, %2, %3;" : "=l"(d) : "l"(a), "l"(b), "l"(c))
#define PACK_F32X2(out, lo, hi) \
    asm("mov.b64 %0, {%1, %2};" : "=l"(out) : "f"(lo), "f"(hi))
#define UNPACK_F32X2(lo, hi, in) \
    asm("mov.b64 {%0, %1}, %2;" : "=f"(lo), "=f"(hi) : "l"(in))

// ---------------- K0: split w into bf16 hi/lo + zero BN stat accumulators ----
__global__ __launch_bounds__(256) void k0_wprep(const float* __restrict__ w)
{
    if (blockIdx.x == 0 && threadIdx.x < H) {
        g_sum[threadIdx.x] = 0.0;
        g_sumsq[threadIdx.x] = 0.0;
    }
    const int total = H * (KPAD / 2);
    for (int e = blockIdx.x * 256 + threadIdx.x; e < total; e += 64 * 256) {
        const int n  = e / (KPAD / 2);
        const int kp = (e % (KPAD / 2)) * 2;
        float2 v = make_float2(0.f, 0.f);
        if (kp < F_IN) v = *(const float2*)(w + (size_t)n * F_IN + kp);
        __nv_bfloat162 hi2 = __floats2bfloat162_rn(v.x, v.y);
        float2 hf = __bfloat1622float2(hi2);
        __nv_bfloat162 lo2 = __floats2bfloat162_rn(v.x - hf.x, v.y - hf.y);
        *(__nv_bfloat162*)(g_wh + (size_t)n * KPAD + kp) = hi2;
        *(__nv_bfloat162*)(g_wl + (size_t)n * KPAD + kp) = lo2;
    }
}

// ---------------- K1: o1 = selu(x @ w^T + b) wmma + fused epilogue/stats -----
#define BK 32
#define NCH (KPAD / BK)   // 25
#define LDS_T 40          // 32 + 8 pad (bf16 elems)
// smem union: bf16 tiles (30720 B) overlaid by 64x128 fp32 result (32768 B)
#define OFF_AH 0
#define OFF_AL 5120
#define OFF_BH 10240
#define OFF_BL 20480

__global__ __launch_bounds__(256) void k1_gemm_wmma(
    const float* __restrict__ x, const float* __restrict__ bias)
{
    __shared__ __align__(16) char smem_buf[32768];
    __nv_bfloat16 (*sAh)[LDS_T] = (__nv_bfloat16 (*)[LDS_T])(smem_buf + OFF_AH);
    __nv_bfloat16 (*sAl)[LDS_T] = (__nv_bfloat16 (*)[LDS_T])(smem_buf + OFF_AL);
    __nv_bfloat16 (*sBh)[LDS_T] = (__nv_bfloat16 (*)[LDS_T])(smem_buf + OFF_BH);
    __nv_bfloat16 (*sBl)[LDS_T] = (__nv_bfloat16 (*)[LDS_T])(smem_buf + OFF_BL);
    float* sOut = (float*)smem_buf;

    const int t = threadIdx.x;
    const int wid = t >> 5;
    const int wr = wid >> 1;           // 0..3  (M quadrant, 16 rows)
    const int wc = wid & 1;            // 0..1  (N half, 64 cols)
    const int row0 = blockIdx.x * 64;

    wmma::fragment<wmma::accumulator, 16, 16, 16, float> acc[4];
#pragma unroll
    for (int j = 0; j < 4; j++) wmma::fill_fragment(acc[j], 0.f);

    for (int c = 0; c < NCH; c++) {
        const int kc = c * BK;
#pragma unroll
        for (int it = 0; it < 4; it++) {
            const int e = t + it * 256;
            const int m  = e >> 4;
            const int kp = (e & 15) * 2;
            const int k  = kc + kp;
            float2 v = make_float2(0.f, 0.f);
            if (k < F_IN) v = *(const float2*)(x + (size_t)(row0 + m) * F_IN + k);
            __nv_bfloat162 hi2 = __floats2bfloat162_rn(v.x, v.y);
            float2 hf = __bfloat1622float2(hi2);
            __nv_bfloat162 lo2 = __floats2bfloat162_rn(v.x - hf.x, v.y - hf.y);
            *(__nv_bfloat162*)(&sAh[m][kp]) = hi2;
            *(__nv_bfloat162*)(&sAl[m][kp]) = lo2;
        }
#pragma unroll
        for (int it = 0; it < 8; it++) {
            const int e = t + it * 256;
            const int n  = e >> 4;
            const int kp = (e & 15) * 2;
            const size_t gi = (size_t)n * KPAD + kc + kp;
            *(uint32_t*)(&sBh[n][kp]) = *(const uint32_t*)(g_wh + gi);
            *(uint32_t*)(&sBl[n][kp]) = *(const uint32_t*)(g_wl + gi);
        }
        __syncthreads();

#pragma unroll
        for (int kk = 0; kk < 2; kk++) {
            wmma::fragment<wmma::matrix_a, 16, 16, 16, __nv_bfloat16, wmma::row_major> ah, al;
            wmma::load_matrix_sync(ah, &sAh[wr * 16][kk * 16], LDS_T);
            wmma::load_matrix_sync(al, &sAl[wr * 16][kk * 16], LDS_T);
#pragma unroll
            for (int j = 0; j < 4; j++) {
                wmma::fragment<wmma::matrix_b, 16, 16, 16, __nv_bfloat16, wmma::col_major> bh, bl;
                wmma::load_matrix_sync(bh, &sBh[wc * 64 + j * 16][kk * 16], LDS_T);
                wmma::load_matrix_sync(bl, &sBl[wc * 64 + j * 16][kk * 16], LDS_T);
                wmma::mma_sync(acc[j], ah, bh, acc[j]);
                wmma::mma_sync(acc[j], ah, bl, acc[j]);
                wmma::mma_sync(acc[j], al, bh, acc[j]);
            }
        }
        __syncthreads();
    }

    // epilogue: stage raw tile in smem, then bias+selu+store+stats
#pragma unroll
    for (int j = 0; j < 4; j++) {
        wmma::store_matrix_sync(sOut + (wr * 16) * H + wc * 64 + j * 16,
                                acc[j], H, wmma::mem_row_major);
    }
    __syncthreads();

    const int col = t & (H - 1);
    const int r0  = (t >> 7) * 32;               // 0 or 32
    const float b = bias[col];
    float s = 0.f, s2 = 0.f;
#pragma unroll 8
    for (int r = r0; r < r0 + 32; r++) {
        float v = selu_f(sOut[r * H + col] + b);
        g_o1[(size_t)(row0 + r) * H + col] = v;
        s += v;
        s2 = fmaf(v, v, s2);
    }
    atomicAdd(&g_sum[col],   (double)s);
    atomicAdd(&g_sumsq[col], (double)s2);
}

// ---------------- K3: BN apply + fc2 + selu -> o[n,2] (4 rows per warp) ------
__global__ __launch_bounds__(256) void k3_bn_fc2(
    const float* __restrict__ gamma, const float* __restrict__ beta,
    const float* __restrict__ w2, const float* __restrict__ b2,
    float* __restrict__ out_tail, int write_tail)
{
    __shared__ float s_scale[H], s_shift[H], s_w0[H], s_w1[H];
    const int t = threadIdx.x;
    if (blockIdx.x == 0 && t == 0) g_denom = 0.0;
    if (t < H) {
        double mean = g_sum[t]   / (double)N_ROWS;
        double var  = g_sumsq[t] / (double)N_ROWS - mean * mean;
        float inv = (float)rsqrt(var + 1e-5);
        float sc  = gamma[t] * inv;
        s_scale[t] = sc;
        s_shift[t] = beta[t] - (float)mean * sc;
        s_w0[t] = w2[t];
        s_w1[t] = w2[H + t];
    }
    __syncthreads();

    const int warp = t >> 5, lane = t & 31;
    const int row = blockIdx.x * 32 + warp * 4;  // grid 256 -> all rows
    const int c = lane * 4;

    float4 v[4];
#pragma unroll
    for (int r = 0; r < 4; r++)
        v[r] = *(const float4*)(g_o1 + (size_t)(row + r) * H + c);

    float d0[4], d1[4];
#pragma unroll
    for (int r = 0; r < 4; r++) {
        float bn;
        d0[r] = 0.f; d1[r] = 0.f;
        bn = fmaf(v[r].x, s_scale[c + 0], s_shift[c + 0]);
        d0[r] = fmaf(bn, s_w0[c + 0], d0[r]); d1[r] = fmaf(bn, s_w1[c + 0], d1[r]);
        bn = fmaf(v[r].y, s_scale[c + 1], s_shift[c + 1]);
        d0[r] = fmaf(bn, s_w0[c + 1], d0[r]); d1[r] = fmaf(bn, s_w1[c + 1], d1[r]);
        bn = fmaf(v[r].z, s_scale[c + 2], s_shift[c + 2]);
        d0[r] = fmaf(bn, s_w0[c + 2], d0[r]); d1[r] = fmaf(bn, s_w1[c + 2], d1[r]);
        bn = fmaf(v[r].w, s_scale[c + 3], s_shift[c + 3]);
        d0[r] = fmaf(bn, s_w0[c + 3], d0[r]); d1[r] = fmaf(bn, s_w1[c + 3], d1[r]);
    }
#pragma unroll
    for (int off = 16; off > 0; off >>= 1) {
#pragma unroll
        for (int r = 0; r < 4; r++) {
            d0[r] += __shfl_down_sync(0xffffffffu, d0[r], off);
            d1[r] += __shfl_down_sync(0xffffffffu, d1[r], off);
        }
    }
    if (lane == 0) {
        const float bb0 = b2[0], bb1 = b2[1];
#pragma unroll
        for (int r = 0; r < 4; r++) {
            float o0 = selu_f(d0[r] + bb0);
            float o1 = selu_f(d1[r] + bb1);
            g_o[row + r] = make_float2(o0, o1);
            if (write_tail) {
                out_tail[(row + r) * 2 + 0] = o0;
                out_tail[(row + r) * 2 + 1] = o1;
            }
        }
    }
}

// ---------------- K4: S = sum_{i<j} 1/(1+d_ij)  (symmetry-halved) ------------
__global__ __launch_bounds__(256) void k4_denom()
{
    __shared__ float sx[JT], sy[JT];
    const int t     = threadIdx.x;
    const int rid   = blockIdx.x >> 3;
    const int jt    = blockIdx.x & 7;
    const int i0    = rid * 8;
    const int jbase = jt * JT;
    if (jbase + JT - 1 <= i0) return;

    const float2* __restrict__ src = g_o + jbase;
    for (int i = t; i < JT; i += 256) {
        float2 v = src[i];
        sx[i] = v.x; sy[i] = v.y;
    }
    float2 p[8];
#pragma unroll
    for (int u = 0; u < 8; u++) p[u] = g_o[i0 + u];
    __syncthreads();

    float acc = 0.f;
    const int j4 = t * 4;
    if (jbase >= i0 + 8) {
        ull m1, on;
        PACK_F32X2(m1, -1.f, -1.f);
        PACK_F32X2(on,  1.f,  1.f);
        ull qx0 = *(const ull*)&sx[j4];
        ull qx1 = *(const ull*)&sx[j4 + 2];
        ull qy0 = *(const ull*)&sy[j4];
        ull qy1 = *(const ull*)&sy[j4 + 2];
        float a0 = 0.f, a1 = 0.f;
#pragma unroll
        for (int u = 0; u < 8; u++) {
            ull ppx, ppy;
            PACK_F32X2(ppx, p[u].x, p[u].x);
            PACK_F32X2(ppy, p[u].y, p[u].y);
            ull dxA, dyA, tA, dA, dxB, dyB, tB, dB;
            FMA_F32X2(dxA, qx0, m1, ppx);
            FMA_F32X2(dyA, qy0, m1, ppy);
            FMA_F32X2(tA, dyA, dyA, on);
            FMA_F32X2(dA, dxA, dxA, tA);
            FMA_F32X2(dxB, qx1, m1, ppx);
            FMA_F32X2(dyB, qy1, m1, ppy);
            FMA_F32X2(tB, dyB, dyB, on);
            FMA_F32X2(dB, dxB, dxB, tB);
            float vA0, vA1, vB0, vB1;
            UNPACK_F32X2(vA0, vA1, dA);
            UNPACK_F32X2(vB0, vB1, dB);
            a0 = fmaf(vA0 + vA1, frcp(vA0 * vA1), a0);
            a1 = fmaf(vB0 + vB1, frcp(vB0 * vB1), a1);
        }
        acc = a0 + a1;
    } else {
#pragma unroll
        for (int uu = 0; uu < 4; uu++) {
            const int j = jbase + j4 + uu;
            const float qx = sx[j4 + uu], qy = sy[j4 + uu];
#pragma unroll
            for (int u = 0; u < 8; u++) {
                const float dx = p[u].x - qx;
                const float dy = p[u].y - qy;
                const float d  = fmaf(dx, dx, fmaf(dy, dy, 1.f));
                if (j > i0 + u) acc += frcp(d);
            }
        }
    }

    float s = acc;
#pragma unroll
    for (int off = 16; off > 0; off >>= 1)
        s += __shfl_down_sync(0xffffffffu, s, off);
    __shared__ float red[8];
    if ((t & 31) == 0) red[t >> 5] = s;
    __syncthreads();
    if (t == 0) {
        float tot = 0.f;
#pragma unroll
        for (int u = 0; u < 8; u++) tot += red[u];
        atomicAdd(&g_denom, (double)tot);
    }
}

// ---------------- K5: qij write; inv = 1/(2*S) folded in ---------------------
__global__ __launch_bounds__(256) void k5_qij(float* __restrict__ out)
{
    __shared__ float sx[JH], sy[JH];
    __shared__ float s_inv;
    const int t    = threadIdx.x;
    const int half = blockIdx.x & 1;
    const int rid  = blockIdx.x >> 1;

    if (t == 0) s_inv = (float)(1.0 / (2.0 * g_denom));
    const float2* __restrict__ src = g_o + half * JH;
    for (int i = t; i < JH; i += 256) {
        float2 v = src[i];
        sx[i] = v.x; sy[i] = v.y;
    }
    __syncthreads();

    const float inv = s_inv;
    ull m1, on;
    PACK_F32X2(m1, -1.f, -1.f);
    PACK_F32X2(on,  1.f,  1.f);

#pragma unroll
    for (int r = 0; r < 8; r++) {
        const int row = rid * 8 + r;
        float2 p = g_o[row];
        ull ppx, ppy;
        PACK_F32X2(ppx, p.x, p.x);
        PACK_F32X2(ppy, p.y, p.y);
        float4* __restrict__ dst = (float4*)(out + (size_t)row * N_ROWS + half * JH);
        for (int c = t; c < JH / 4; c += 256) {
            ull qx0 = *(const ull*)&sx[c * 4];
            ull qx1 = *(const ull*)&sx[c * 4 + 2];
            ull qy0 = *(const ull*)&sy[c * 4];
            ull qy1 = *(const ull*)&sy[c * 4 + 2];
            ull dxA, dyA, tA, dA, dxB, dyB, tB, dB;
            FMA_F32X2(dxA, qx0, m1, ppx);
            FMA_F32X2(dyA, qy0, m1, ppy);
            FMA_F32X2(tA, dyA, dyA, on);
            FMA_F32X2(dA, dxA, dxA, tA);
            FMA_F32X2(dxB, qx1, m1, ppx);
            FMA_F32X2(dyB, qy1, m1, ppy);
            FMA_F32X2(tB, dyB, dyB, on);
            FMA_F32X2(dB, dxB, dxB, tB);
            float d0, d1, d2, d3;
            UNPACK_F32X2(d0, d1, dA);
            UNPACK_F32X2(d2, d3, dB);
            float4 o4;
            o4.x = frcp(d0) * inv;
            o4.y = frcp(d1) * inv;
            o4.z = frcp(d2) * inv;
            o4.w = frcp(d3) * inv;
            __stcs(dst + c, o4);
        }
    }
}

// ---------------- launch -----------------------------------------------------
extern "C" void kernel_launch(void* const* d_in, const int* in_sizes, int n_in,
                              void* d_out, int out_size)
{
    const float* x     = (const float*)d_in[0];
    const float* fcw   = (const float*)d_in[1];
    const float* fcb   = (const float*)d_in[2];
    const float* gamma = (const float*)d_in[3];
    const float* beta  = (const float*)d_in[4];
    const float* w2    = (const float*)d_in[5];
    const float* b2    = (const float*)d_in[6];
    float* out = (float*)d_out;

    const size_t nq = (size_t)N_ROWS * N_ROWS;
    const int write_tail = ((size_t)out_size > nq) ? 1 : 0;

    k0_wprep<<<64, 256>>>(fcw);
    k1_gemm_wmma<<<128, 256>>>(x, fcb);
    k3_bn_fc2<<<256, 256>>>(gamma, beta, w2, b2, out + nq, write_tail);
    k4_denom<<<8192, 256>>>();
    k5_qij<<<2048, 256>>>(out);
}